// round 13
// baseline (speedup 1.0000x reference)
#include <cuda_runtime.h>
#include <cstdint>

#define BATCH   1024
#define FDIM    2048
#define LDIM    80
#define EDIM    512
#define IN_DIM  2560
#define ODIM    2048
#define NEXP    8

// GEMM config: CTA 64x128 (4 warps, 2m x 2n, warp tile 32x64), BK=64, 128 thr.
// 2 CTAs co-resident per SM. A direct from L2 (k-pair rolling prefetch).
// B staged in SMEM (3-stage cp.async) with SOFTWARE-PIPELINED LDS: alternating
// bA/bB k-step register buffers so LDS crossbar overlaps MMA execution.
// Dual accumulators; fp32 gate-merge at expert boundaries.
#define BM 64
#define BN 128
#define BK 64
#define STAGES 3
#define NTHR 128
#define ITER_PER_E (IN_DIM / BK)     // 40
#define NIT ((NEXP * IN_DIM) / BK)   // 320
#define B_ROW_F   136                // 128 + 8 pad (conflict-free)
#define B_STAGE_F (BK * B_ROW_F)     // 8704 floats
#define SMEM_F (STAGES * B_STAGE_F + 512 + 1024)
#define SMEM_BYTES (SMEM_F * 4)      // ~110.6 KB -> 2 CTAs/SM

// -------- scratch (static device globals) --------
__device__ float g_gating[BATCH * NEXP];
__device__ float g_cpack[(size_t)BATCH * IN_DIM];   // 10.5 MB, fragment-packed tf32

// ======================= helpers =======================
__device__ __forceinline__ uint32_t smem_u32(const void* p) {
    uint32_t a;
    asm("{ .reg .u64 t; cvta.to.shared.u64 t, %1; cvt.u32.u64 %0, t; }" : "=r"(a) : "l"(p));
    return a;
}
__device__ __forceinline__ float tf32_rna(float x) {
    float y;
    asm("cvt.rna.tf32.f32 %0, %1;" : "=f"(y) : "f"(x));
    return y;
}
#define CP16(dst, src) \
    asm volatile("cp.async.cg.shared.global [%0], [%1], 16;" :: "r"(dst), "l"(src))
#define CP_COMMIT() asm volatile("cp.async.commit_group;" ::: "memory")
#define CP_WAIT(n)  asm volatile("cp.async.wait_group %0;" :: "n"(n) : "memory")

__device__ __forceinline__ void mma_tf32(float* d, const uint32_t* a, const uint32_t* b) {
    asm volatile(
        "mma.sync.aligned.m16n8k8.row.col.f32.tf32.tf32.f32 "
        "{%0,%1,%2,%3}, {%4,%5,%6,%7}, {%8,%9}, {%0,%1,%2,%3};"
        : "+f"(d[0]), "+f"(d[1]), "+f"(d[2]), "+f"(d[3])
        : "r"(a[0]), "r"(a[1]), "r"(a[2]), "r"(a[3]), "r"(b[0]), "r"(b[1]));
}

// ======================= Prologue =======================
// One block per batch row b: label-embed, concat, gating (sigmoid),
// and write c (tf32-rounded) PRE-PACKED in m16n8k8 A-fragment order.
__global__ __launch_bounds__(256) void moe_prologue(
    const float* __restrict__ feat, const float* __restrict__ labels,
    const float* __restrict__ lemb, const float* __restrict__ gw,
    const float* __restrict__ gb)
{
    int b = blockIdx.x, tid = threadIdx.x;
    __shared__ float s_lab[LDIM];
    __shared__ float s_c[IN_DIM];
    __shared__ float s_red[NEXP * 8];

    if (tid < LDIM) s_lab[tid] = labels[(size_t)b * LDIM + tid];
    const float4* f4 = reinterpret_cast<const float4*>(feat + (size_t)b * FDIM);
    float4* c4 = reinterpret_cast<float4*>(s_c);
    for (int i = tid; i < FDIM / 4; i += 256) c4[i] = f4[i];
    __syncthreads();

    for (int j = tid; j < EDIM; j += 256) {
        float acc = 0.f;
        #pragma unroll 8
        for (int l = 0; l < LDIM; ++l) acc += s_lab[l] * lemb[l * EDIM + j];
        s_c[FDIM + j] = acc;
    }
    __syncthreads();

    float acc[NEXP];
    #pragma unroll
    for (int e = 0; e < NEXP; ++e) acc[e] = 0.f;
    for (int k = tid; k < IN_DIM; k += 256) {
        float cv = s_c[k];
        const float4* w4 = reinterpret_cast<const float4*>(gw + (size_t)k * NEXP);
        float4 w0 = w4[0], w1 = w4[1];
        acc[0] += cv * w0.x; acc[1] += cv * w0.y; acc[2] += cv * w0.z; acc[3] += cv * w0.w;
        acc[4] += cv * w1.x; acc[5] += cv * w1.y; acc[6] += cv * w1.z; acc[7] += cv * w1.w;
    }
    int lane = tid & 31, wid = tid >> 5;
    #pragma unroll
    for (int e = 0; e < NEXP; ++e) {
        float v = acc[e];
        v += __shfl_xor_sync(0xffffffff, v, 16);
        v += __shfl_xor_sync(0xffffffff, v, 8);
        v += __shfl_xor_sync(0xffffffff, v, 4);
        v += __shfl_xor_sync(0xffffffff, v, 2);
        v += __shfl_xor_sync(0xffffffff, v, 1);
        if (lane == 0) s_red[e * 8 + wid] = v;
    }
    __syncthreads();
    if (tid < NEXP) {
        float z = gb[tid];
        #pragma unroll
        for (int w = 0; w < 8; ++w) z += s_red[tid * 8 + w];
        g_gating[(size_t)b * NEXP + tid] = 1.f / (1.f + __expf(-z));
    }

    int mt = b >> 7, rl = b & 127, mb = rl >> 4, r16 = rl & 15;
    int row_part = (r16 & 7) * 16 + (r16 >> 3);
    for (int i = tid; i < IN_DIM; i += 256) {
        int kb = i >> 3, kk = i & 7;
        int off = row_part + (kk & 3) * 4 + (kk >> 2) * 2;
        size_t idx = ((size_t)((mt * 320 + kb) * 8 + mb)) * 128 + off;
        g_cpack[idx] = tf32_rna(s_c[i]);
    }
}

// ======================= Main GEMM kernel =======================
__global__ __launch_bounds__(NTHR, 2) void moe_gemm(
    const float* __restrict__ expert_w, const float* __restrict__ expert_b,
    float* __restrict__ out)
{
    extern __shared__ float smem[];
    float* Bs     = smem;                          // STAGES * 8704
    float* g_s    = Bs + STAGES * B_STAGE_F;       // 64*8
    float* bias_s = g_s + 512;                     // 8*128

    const int tid = threadIdx.x;
    const int wid = tid >> 5, lane = tid & 31;
    const int wm = wid & 1, wn = wid >> 1;         // 2m x 2n, warp tile 32x64
    const int n0 = blockIdx.x * BN;
    const int m0 = blockIdx.y * BM;
    const int mt128 = blockIdx.y >> 1;             // 128-row pack tile
    const int mhalf = blockIdx.y & 1;              // which 64-row half
    const int nrow = lane >> 2, kcol = lane & 3;

    const uint32_t Bs_a = smem_u32(Bs);

    float acc_o[2][8][4];
    float acc_e[2][8][4];
    #pragma unroll
    for (int f = 0; f < 2; ++f)
        #pragma unroll
        for (int g = 0; g < 8; ++g)
            #pragma unroll
            for (int c = 0; c < 4; ++c) { acc_o[f][g][c] = 0.f; acc_e[f][g][c] = 0.f; }

    // ---- B stage issue: 64 rows x 512B, 16 CP16 per thread ----
    auto issueB = [&](int slot, int it) {
        const float* bsrc = expert_w + (size_t)it * BK * ODIM + n0;  // experts contiguous
        uint32_t bdst = Bs_a + slot * (B_STAGE_F * 4);
        #pragma unroll
        for (int j = 0; j < 16; ++j) {
            int u = tid + NTHR * j;
            int r = u >> 5, ch = u & 31;
            CP16(bdst + r * (B_ROW_F * 4) + ch * 16, bsrc + (size_t)r * ODIM + ch * 4);
        }
    };

    issueB(0, 0); CP_COMMIT();
    issueB(1, 1); CP_COMMIT();

    // gating + bias slices (visible after first in-loop __syncthreads)
    for (int i = tid; i < BM * NEXP; i += NTHR) {
        int r = i >> 3, e = i & 7;
        g_s[r * 8 + e] = g_gating[(size_t)(m0 + r) * NEXP + e];
    }
    for (int i = tid; i < NEXP * BN; i += NTHR) {
        int e = i >> 7, c = i & 127;
        bias_s[e * 128 + c] = expert_b[(size_t)e * ODIM + n0 + c];
    }

    // A fragment base: pack layout idx = ((mt128*320 + kbl)*8 + mb16)*128 + off
    // this CTA's rows use mb16 = mhalf*4 + wm*2 + f
    const float* const apack = g_cpack + (size_t)(mt128 * 320) * 1024
                               + (size_t)(mhalf * 4 + wm * 2) * 128 + lane * 4;
    const float* const aend  = apack + (size_t)320 * 1024;

    // A k-pair buffers (pair = 2 consecutive k8-blocks): aE holds even pairs,
    // aO odd pairs. Rolling prefetch pointer wraps at the 320-kbl boundary.
    uint4 aE[2][2], aO[2][2];   // [k-in-pair][f]
    #pragma unroll
    for (int k = 0; k < 2; ++k)
        #pragma unroll
        for (int f = 0; f < 2; ++f) {
            aE[k][f] = *reinterpret_cast<const uint4*>(apack + (size_t)k * 1024 + f * 128);
            aO[k][f] = *reinterpret_cast<const uint4*>(apack + (size_t)(2 + k) * 1024 + f * 128);
        }
    const float* aptr = apack + (size_t)4 * 1024;   // next pair to prefetch

    // B k-step register buffers (software pipeline)
    uint32_t bA[8][2], bB[8][2];

#define LDB_K(breg, kk) do { \
    _Pragma("unroll") \
    for (int g = 0; g < 8; ++g) { \
        int nidx = wn * 64 + g * 8 + nrow; \
        (breg)[g][0] = __float_as_uint(bst[(kk) * 8 * B_ROW_F + kcol * B_ROW_F + nidx]); \
        (breg)[g][1] = __float_as_uint(bst[((kk) * 8 + 4) * B_ROW_F + kcol * B_ROW_F + nidx]); \
    } \
} while (0)

#define MMA_ALL(breg, afr) do { \
    _Pragma("unroll") \
    for (int f = 0; f < 2; ++f) { \
        const uint32_t* _a = reinterpret_cast<const uint32_t*>(&(afr)[f]); \
        _Pragma("unroll") \
        for (int g = 0; g < 8; ++g) \
            mma_tf32(acc_e[f][g], _a, (breg)[g]); \
    } \
} while (0)

#define PREF_A(buf) do { \
    (buf)[0][0] = *reinterpret_cast<const uint4*>(aptr); \
    (buf)[0][1] = *reinterpret_cast<const uint4*>(aptr + 128); \
    (buf)[1][0] = *reinterpret_cast<const uint4*>(aptr + 1024); \
    (buf)[1][1] = *reinterpret_cast<const uint4*>(aptr + 1024 + 128); \
    aptr += 2048; \
    if (aptr >= aend) aptr = apack; \
} while (0)

    int slot = 0, ii = 0, eC = 0;

    for (int it = 0; it < NIT; ++it) {
        CP_WAIT(1);                 // oldest of 2 pending = stage `it`
        __syncthreads();
        if (it + 2 < NIT) {
            int s2 = slot + 2; if (s2 >= STAGES) s2 -= STAGES;
            issueB(s2, it + 2);
        }
        CP_COMMIT();

        const float* bst = Bs + slot * B_STAGE_F;

        // software-pipelined 8 k-steps: LDS for k+1 issued before MMAs of k
        LDB_K(bA, 0);
        // pair 0 (k=0,1) uses aE
        LDB_K(bB, 1);
        MMA_ALL(bA, aE[0]);
        LDB_K(bA, 2);
        MMA_ALL(bB, aE[1]);
        PREF_A(aE);                 // pair 2
        // pair 1 (k=2,3) uses aO
        LDB_K(bB, 3);
        MMA_ALL(bA, aO[0]);
        LDB_K(bA, 4);
        MMA_ALL(bB, aO[1]);
        PREF_A(aO);                 // pair 3
        // pair 2 (k=4,5) uses aE
        LDB_K(bB, 5);
        MMA_ALL(bA, aE[0]);
        LDB_K(bA, 6);
        MMA_ALL(bB, aE[1]);
        PREF_A(aE);                 // pair 4 = next iter pair 0
        // pair 3 (k=6,7) uses aO
        LDB_K(bB, 7);
        MMA_ALL(bA, aO[0]);
        MMA_ALL(bB, aO[1]);
        PREF_A(aO);                 // pair 5 = next iter pair 1

        // ---- expert boundary: fp32 gate-merge into output accumulator ----
        if (ii == ITER_PER_E - 1) {
            #pragma unroll
            for (int f = 0; f < 2; ++f) {
                int rl = wm * 32 + f * 16 + nrow;
                float gl = g_s[rl * 8 + eC];
                float gh = g_s[(rl + 8) * 8 + eC];
                #pragma unroll
                for (int g = 0; g < 8; ++g) {
                    acc_o[f][g][0] += gl * acc_e[f][g][0];
                    acc_o[f][g][1] += gl * acc_e[f][g][1];
                    acc_o[f][g][2] += gh * acc_e[f][g][2];
                    acc_o[f][g][3] += gh * acc_e[f][g][3];
                    acc_e[f][g][0] = 0.f; acc_e[f][g][1] = 0.f;
                    acc_e[f][g][2] = 0.f; acc_e[f][g][3] = 0.f;
                }
            }
        }

        // counters
        if (++slot == STAGES) slot = 0;
        if (++ii == ITER_PER_E) { ii = 0; ++eC; }
    }

    // ---- epilogue: gated bias + store ----
    #pragma unroll
    for (int f = 0; f < 2; ++f) {
        int rl = wm * 32 + f * 16 + nrow;
        int rh = rl + 8;
        #pragma unroll
        for (int g = 0; g < 8; ++g) {
            int cb = wn * 64 + g * 8 + 2 * kcol;
            float bl0 = 0.f, bl1 = 0.f, bh0 = 0.f, bh1 = 0.f;
            #pragma unroll
            for (int e = 0; e < NEXP; ++e) {
                float gle = g_s[rl * 8 + e], ghe = g_s[rh * 8 + e];
                float b0v = bias_s[e * 128 + cb], b1v = bias_s[e * 128 + cb + 1];
                bl0 += gle * b0v; bl1 += gle * b1v;
                bh0 += ghe * b0v; bh1 += ghe * b1v;
            }
            float2 lo = make_float2(acc_o[f][g][0] + bl0, acc_o[f][g][1] + bl1);
            float2 hi = make_float2(acc_o[f][g][2] + bh0, acc_o[f][g][3] + bh1);
            *reinterpret_cast<float2*>(out + (size_t)(m0 + rl) * ODIM + n0 + cb) = lo;
            *reinterpret_cast<float2*>(out + (size_t)(m0 + rh) * ODIM + n0 + cb) = hi;
        }
    }
}

// ======================= launch =======================
extern "C" void kernel_launch(void* const* d_in, const int* in_sizes, int n_in,
                              void* d_out, int out_size) {
    const float* feat   = (const float*)d_in[0];
    const float* labels = (const float*)d_in[1];
    const float* lemb   = (const float*)d_in[2];
    const float* gw     = (const float*)d_in[3];
    const float* gb     = (const float*)d_in[4];
    const float* ew     = (const float*)d_in[5];
    const float* eb     = (const float*)d_in[6];
    float* out = (float*)d_out;

    moe_prologue<<<BATCH, 256>>>(feat, labels, lemb, gw, gb);

    cudaFuncSetAttribute(moe_gemm, cudaFuncAttributeMaxDynamicSharedMemorySize, SMEM_BYTES);
    dim3 grid(ODIM / BN, BATCH / BM);   // 16 x 16 = 256 CTAs, 2 per SM
    moe_gemm<<<grid, NTHR, SMEM_BYTES>>>(ew, eb, out);
}

// round 14
// speedup vs baseline: 1.1200x; 1.1200x over previous
#include <cuda_runtime.h>
#include <cstdint>

#define BATCH   1024
#define FDIM    2048
#define LDIM    80
#define EDIM    512
#define IN_DIM  2560
#define ODIM    2048
#define NEXP    8

// GEMM config: CTA 64x128 (4 warps, 2m x 2n, warp tile 32x64), BK=64, 128 thr.
// 2 CTAs co-resident per SM. A direct from L2 (half-iter ping-pong regs, raw
// tf32 bits feed MMA directly). B staged in SMEM (3-stage cp.async).
// SINGLE accumulator via telescoping gates: accumulate raw S_e; at expert
// boundary acc *= g_e/g_{e+1}; final acc *= g_7.  (frees 64 regs vs dual-acc)
#define BM 64
#define BN 128
#define BK 64
#define STAGES 3
#define NTHR 128
#define ITER_PER_E (IN_DIM / BK)     // 40
#define NIT ((NEXP * IN_DIM) / BK)   // 320
#define B_ROW_F   136                // 128 + 8 pad (conflict-free)
#define B_STAGE_F (BK * B_ROW_F)     // 8704 floats
#define SMEM_F (STAGES * B_STAGE_F + 512 + 1024)
#define SMEM_BYTES (SMEM_F * 4)      // ~110.6 KB -> 2 CTAs/SM

// -------- scratch (static device globals) --------
__device__ float g_gating[BATCH * NEXP];
__device__ float g_cpack[(size_t)BATCH * IN_DIM];   // 10.5 MB, fragment-packed tf32

// ======================= helpers =======================
__device__ __forceinline__ uint32_t smem_u32(const void* p) {
    uint32_t a;
    asm("{ .reg .u64 t; cvta.to.shared.u64 t, %1; cvt.u32.u64 %0, t; }" : "=r"(a) : "l"(p));
    return a;
}
__device__ __forceinline__ float tf32_rna(float x) {
    float y;
    asm("cvt.rna.tf32.f32 %0, %1;" : "=f"(y) : "f"(x));
    return y;
}
#define CP16(dst, src) \
    asm volatile("cp.async.cg.shared.global [%0], [%1], 16;" :: "r"(dst), "l"(src))
#define CP_COMMIT() asm volatile("cp.async.commit_group;" ::: "memory")
#define CP_WAIT(n)  asm volatile("cp.async.wait_group %0;" :: "n"(n) : "memory")

__device__ __forceinline__ void mma_tf32(float* d, const uint32_t* a, const uint32_t* b) {
    asm volatile(
        "mma.sync.aligned.m16n8k8.row.col.f32.tf32.tf32.f32 "
        "{%0,%1,%2,%3}, {%4,%5,%6,%7}, {%8,%9}, {%0,%1,%2,%3};"
        : "+f"(d[0]), "+f"(d[1]), "+f"(d[2]), "+f"(d[3])
        : "r"(a[0]), "r"(a[1]), "r"(a[2]), "r"(a[3]), "r"(b[0]), "r"(b[1]));
}

// ======================= Prologue =======================
// One block per batch row b: label-embed, concat, gating (sigmoid),
// and write c (tf32-rounded) PRE-PACKED in m16n8k8 A-fragment order.
__global__ __launch_bounds__(256) void moe_prologue(
    const float* __restrict__ feat, const float* __restrict__ labels,
    const float* __restrict__ lemb, const float* __restrict__ gw,
    const float* __restrict__ gb)
{
    int b = blockIdx.x, tid = threadIdx.x;
    __shared__ float s_lab[LDIM];
    __shared__ float s_c[IN_DIM];
    __shared__ float s_red[NEXP * 8];

    if (tid < LDIM) s_lab[tid] = labels[(size_t)b * LDIM + tid];
    const float4* f4 = reinterpret_cast<const float4*>(feat + (size_t)b * FDIM);
    float4* c4 = reinterpret_cast<float4*>(s_c);
    for (int i = tid; i < FDIM / 4; i += 256) c4[i] = f4[i];
    __syncthreads();

    for (int j = tid; j < EDIM; j += 256) {
        float acc = 0.f;
        #pragma unroll 8
        for (int l = 0; l < LDIM; ++l) acc += s_lab[l] * lemb[l * EDIM + j];
        s_c[FDIM + j] = acc;
    }
    __syncthreads();

    float acc[NEXP];
    #pragma unroll
    for (int e = 0; e < NEXP; ++e) acc[e] = 0.f;
    for (int k = tid; k < IN_DIM; k += 256) {
        float cv = s_c[k];
        const float4* w4 = reinterpret_cast<const float4*>(gw + (size_t)k * NEXP);
        float4 w0 = w4[0], w1 = w4[1];
        acc[0] += cv * w0.x; acc[1] += cv * w0.y; acc[2] += cv * w0.z; acc[3] += cv * w0.w;
        acc[4] += cv * w1.x; acc[5] += cv * w1.y; acc[6] += cv * w1.z; acc[7] += cv * w1.w;
    }
    int lane = tid & 31, wid = tid >> 5;
    #pragma unroll
    for (int e = 0; e < NEXP; ++e) {
        float v = acc[e];
        v += __shfl_xor_sync(0xffffffff, v, 16);
        v += __shfl_xor_sync(0xffffffff, v, 8);
        v += __shfl_xor_sync(0xffffffff, v, 4);
        v += __shfl_xor_sync(0xffffffff, v, 2);
        v += __shfl_xor_sync(0xffffffff, v, 1);
        if (lane == 0) s_red[e * 8 + wid] = v;
    }
    __syncthreads();
    if (tid < NEXP) {
        float z = gb[tid];
        #pragma unroll
        for (int w = 0; w < 8; ++w) z += s_red[tid * 8 + w];
        g_gating[(size_t)b * NEXP + tid] = 1.f / (1.f + __expf(-z));
    }

    int mt = b >> 7, rl = b & 127, mb = rl >> 4, r16 = rl & 15;
    int row_part = (r16 & 7) * 16 + (r16 >> 3);
    for (int i = tid; i < IN_DIM; i += 256) {
        int kb = i >> 3, kk = i & 7;
        int off = row_part + (kk & 3) * 4 + (kk >> 2) * 2;
        size_t idx = ((size_t)((mt * 320 + kb) * 8 + mb)) * 128 + off;
        g_cpack[idx] = tf32_rna(s_c[i]);
    }
}

// ======================= Main GEMM kernel =======================
__global__ __launch_bounds__(NTHR, 2) void moe_gemm(
    const float* __restrict__ expert_w, const float* __restrict__ expert_b,
    float* __restrict__ out)
{
    extern __shared__ float smem[];
    float* Bs     = smem;                          // STAGES * 8704
    float* g_s    = Bs + STAGES * B_STAGE_F;       // 64*8
    float* bias_s = g_s + 512;                     // 8*128

    const int tid = threadIdx.x;
    const int wid = tid >> 5, lane = tid & 31;
    const int wm = wid & 1, wn = wid >> 1;         // 2m x 2n, warp tile 32x64
    const int n0 = blockIdx.x * BN;
    const int m0 = blockIdx.y * BM;
    const int mt128 = blockIdx.y >> 1;             // 128-row pack tile
    const int mhalf = blockIdx.y & 1;              // which 64-row half
    const int nrow = lane >> 2, kcol = lane & 3;

    const uint32_t Bs_a = smem_u32(Bs);

    float acc[2][8][4];
    #pragma unroll
    for (int f = 0; f < 2; ++f)
        #pragma unroll
        for (int g = 0; g < 8; ++g)
            #pragma unroll
            for (int c = 0; c < 4; ++c) acc[f][g][c] = 0.f;

    // ---- B stage issue: 64 rows x 512B, 16 CP16 per thread ----
    auto issueB = [&](int slot, int it) {
        const float* bsrc = expert_w + (size_t)it * BK * ODIM + n0;  // experts contiguous
        uint32_t bdst = Bs_a + slot * (B_STAGE_F * 4);
        #pragma unroll
        for (int j = 0; j < 16; ++j) {
            int u = tid + NTHR * j;
            int r = u >> 5, ch = u & 31;
            CP16(bdst + r * (B_ROW_F * 4) + ch * 16, bsrc + (size_t)r * ODIM + ch * 4);
        }
    };

    issueB(0, 0); CP_COMMIT();
    issueB(1, 1); CP_COMMIT();

    // gating + bias slices (visible after first in-loop __syncthreads)
    for (int i = tid; i < BM * NEXP; i += NTHR) {
        int r = i >> 3, e = i & 7;
        g_s[r * 8 + e] = g_gating[(size_t)(m0 + r) * NEXP + e];
    }
    for (int i = tid; i < NEXP * BN; i += NTHR) {
        int e = i >> 7, c = i & 127;
        bias_s[e * 128 + c] = expert_b[(size_t)e * ODIM + n0 + c];
    }

    // A fragment base: pack layout idx = ((mt128*320 + kbl)*8 + mb16)*128 + off
    // this CTA's rows use mb16 = mhalf*4 + wm*2 + f
    const float* const apack = g_cpack + (size_t)(mt128 * 320) * 1024
                               + (size_t)(mhalf * 4 + wm * 2) * 128 + lane * 4;

    uint4 buf0[4][2], buf1[4][2];
    #pragma unroll
    for (int k = 0; k < 4; ++k)
        #pragma unroll
        for (int f = 0; f < 2; ++f)
            buf0[k][f] = *reinterpret_cast<const uint4*>(apack + (size_t)k * 1024 + f * 128);

    // current-expert gates per accumulator row (telescoping scheme)
    float gcl[2], gch[2];
    {
        // gates become visible only after first __syncthreads below; but expert-0
        // gates are read at the FIRST boundary (it=39) — load lazily there.
        gcl[0] = gcl[1] = gch[0] = gch[1] = 0.f;  // placeholder, set at first use
    }

    int slot = 0, ii = 0, eC = 0;
    bool gates_loaded = false;

    for (int it = 0; it < NIT; ++it) {
        // prefetch buf1: current iter, k=4..7 (flies during CP_WAIT)
        #pragma unroll
        for (int k = 0; k < 4; ++k)
            #pragma unroll
            for (int f = 0; f < 2; ++f)
                buf1[k][f] = *reinterpret_cast<const uint4*>(
                    apack + (size_t)(ii * 8 + 4 + k) * 1024 + f * 128);

        CP_WAIT(1);                 // oldest of 2 pending = stage `it`
        __syncthreads();
        if (it + 2 < NIT) {
            int s2 = slot + 2; if (s2 >= STAGES) s2 -= STAGES;
            issueB(s2, it + 2);
        }
        CP_COMMIT();

        if (!gates_loaded) {        // after first barrier: g_s is visible
            #pragma unroll
            for (int f = 0; f < 2; ++f) {
                int rl = wm * 32 + f * 16 + nrow;
                gcl[f] = fmaxf(g_s[rl * 8 + 0], 1e-30f);
                gch[f] = fmaxf(g_s[(rl + 8) * 8 + 0], 1e-30f);
            }
            gates_loaded = true;
        }

        const float* bst = Bs + slot * B_STAGE_F;

        // ---- compute k=0..3 from buf0 (raw tf32 bits straight to MMA) ----
        #pragma unroll
        for (int k = 0; k < 4; ++k) {
            uint32_t b[8][2];
            #pragma unroll
            for (int g = 0; g < 8; ++g) {
                int nidx = wn * 64 + g * 8 + nrow;
                b[g][0] = __float_as_uint(bst[(k * 8 + kcol) * B_ROW_F + nidx]);
                b[g][1] = __float_as_uint(bst[(k * 8 + kcol + 4) * B_ROW_F + nidx]);
            }
            #pragma unroll
            for (int f = 0; f < 2; ++f) {
                const uint32_t* a = reinterpret_cast<const uint32_t*>(&buf0[k][f]);
                #pragma unroll
                for (int g = 0; g < 8; ++g)
                    mma_tf32(acc[f][g], a, b[g]);
            }
        }

        // prefetch buf0 for next iter, k=0..3 (covered by second compute block)
        int iin = ii + 1; if (iin == ITER_PER_E) iin = 0;
        #pragma unroll
        for (int k = 0; k < 4; ++k)
            #pragma unroll
            for (int f = 0; f < 2; ++f)
                buf0[k][f] = *reinterpret_cast<const uint4*>(
                    apack + (size_t)(iin * 8 + k) * 1024 + f * 128);

        // ---- compute k=4..7 from buf1 ----
        #pragma unroll
        for (int k = 0; k < 4; ++k) {
            uint32_t b[8][2];
            #pragma unroll
            for (int g = 0; g < 8; ++g) {
                int nidx = wn * 64 + g * 8 + nrow;
                b[g][0] = __float_as_uint(bst[((k + 4) * 8 + kcol) * B_ROW_F + nidx]);
                b[g][1] = __float_as_uint(bst[((k + 4) * 8 + kcol + 4) * B_ROW_F + nidx]);
            }
            #pragma unroll
            for (int f = 0; f < 2; ++f) {
                const uint32_t* a = reinterpret_cast<const uint32_t*>(&buf1[k][f]);
                #pragma unroll
                for (int g = 0; g < 8; ++g)
                    mma_tf32(acc[f][g], a, b[g]);
            }
        }

        // ---- expert boundary: telescoping rescale acc *= g_e / g_{e+1} ----
        if (ii == ITER_PER_E - 1 && eC < NEXP - 1) {
            #pragma unroll
            for (int f = 0; f < 2; ++f) {
                int rl = wm * 32 + f * 16 + nrow;
                float gnl = fmaxf(g_s[rl * 8 + eC + 1], 1e-30f);
                float gnh = fmaxf(g_s[(rl + 8) * 8 + eC + 1], 1e-30f);
                float sl = gcl[f] / gnl;
                float sh = gch[f] / gnh;
                gcl[f] = gnl; gch[f] = gnh;
                #pragma unroll
                for (int g = 0; g < 8; ++g) {
                    acc[f][g][0] *= sl; acc[f][g][1] *= sl;
                    acc[f][g][2] *= sh; acc[f][g][3] *= sh;
                }
            }
        }

        // counters
        if (++slot == STAGES) slot = 0;
        if (++ii == ITER_PER_E) { ii = 0; ++eC; }
    }

    // ---- epilogue: final gate scale + gated bias + store ----
    #pragma unroll
    for (int f = 0; f < 2; ++f) {
        int rl = wm * 32 + f * 16 + nrow;
        int rh = rl + 8;
        #pragma unroll
        for (int g = 0; g < 8; ++g) {
            int cb = wn * 64 + g * 8 + 2 * kcol;
            float bl0 = 0.f, bl1 = 0.f, bh0 = 0.f, bh1 = 0.f;
            #pragma unroll
            for (int e = 0; e < NEXP; ++e) {
                float gle = g_s[rl * 8 + e], ghe = g_s[rh * 8 + e];
                float b0v = bias_s[e * 128 + cb], b1v = bias_s[e * 128 + cb + 1];
                bl0 += gle * b0v; bl1 += gle * b1v;
                bh0 += ghe * b0v; bh1 += ghe * b1v;
            }
            float2 lo = make_float2(acc[f][g][0] * gcl[f] + bl0, acc[f][g][1] * gcl[f] + bl1);
            float2 hi = make_float2(acc[f][g][2] * gch[f] + bh0, acc[f][g][3] * gch[f] + bh1);
            *reinterpret_cast<float2*>(out + (size_t)(m0 + rl) * ODIM + n0 + cb) = lo;
            *reinterpret_cast<float2*>(out + (size_t)(m0 + rh) * ODIM + n0 + cb) = hi;
        }
    }
}

// ======================= launch =======================
extern "C" void kernel_launch(void* const* d_in, const int* in_sizes, int n_in,
                              void* d_out, int out_size) {
    const float* feat   = (const float*)d_in[0];
    const float* labels = (const float*)d_in[1];
    const float* lemb   = (const float*)d_in[2];
    const float* gw     = (const float*)d_in[3];
    const float* gb     = (const float*)d_in[4];
    const float* ew     = (const float*)d_in[5];
    const float* eb     = (const float*)d_in[6];
    float* out = (float*)d_out;

    moe_prologue<<<BATCH, 256>>>(feat, labels, lemb, gw, gb);

    cudaFuncSetAttribute(moe_gemm, cudaFuncAttributeMaxDynamicSharedMemorySize, SMEM_BYTES);
    dim3 grid(ODIM / BN, BATCH / BM);   // 16 x 16 = 256 CTAs, 2 per SM
    moe_gemm<<<grid, NTHR, SMEM_BYTES>>>(ew, eb, out);
}